// round 14
// baseline (speedup 1.0000x reference)
#include <cuda_runtime.h>
#include <math.h>

#define S_  512
#define B_  32
#define I_  128
#define H_  1024
#define O_  128
#define GRID 148
#define TPB  512

typedef unsigned long long u64;

// ---------------- device scratch (static globals; no allocation) ----------------
// Paired activation layout P(k,b): float offset (k>>1)*64 + b*2 + (k&1).
// As u64 array: pair p (k=2p,2p+1) for batch b lives at u64 index p*32 + b.
__device__ __align__(16) float g_xP[S_ * I_ * B_];   // x per timestep, P layout
__device__ __align__(16) float g_h[3][2][H_ * B_];   // ping-pong hidden (P layout)
__device__ __align__(16) float g_z[3][H_ * B_];      // z gate (P layout)
__device__ __align__(16) float g_r[3][H_ * B_];      // r gate (P layout)
__device__ __align__(16) float g_gx[3][H_ * B_];     // g x-side pre-act + bias: [j*32+b]
__device__ __align__(16) float g_h2[S_][H_ * B_];    // layer-2 hidden history (P layout)
__device__ __align__(16) float g_zero[H_ * B_];      // zeros (layer-2 t=0)
__device__ unsigned g_ctr;                           // grid barrier counter

// ---------------- packed fp32x2 helpers ------------------------------------------
__device__ __forceinline__ u64 fma2(u64 a, u64 b, u64 c) {
    u64 d;
    asm("fma.rn.f32x2 %0, %1, %2, %3;" : "=l"(d) : "l"(a), "l"(b), "l"(c));
    return d;
}
__device__ __forceinline__ u64 mul2(u64 a, u64 b) {
    u64 d;
    asm("mul.rn.f32x2 %0, %1, %2;" : "=l"(d) : "l"(a), "l"(b));
    return d;
}
__device__ __forceinline__ float pairsum(u64 v) {
    float lo, hi;
    asm("mov.b64 {%0, %1}, %2;" : "=f"(lo), "=f"(hi) : "l"(v));
    return lo + hi;
}
__device__ __forceinline__ float sigm(float x) { return 1.0f / (1.0f + expf(-x)); }

// ---------------- software grid barrier ------------------------------------------
// All 148 blocks are co-resident (1 block/SM via launch_bounds + 32KB smem), so
// spinning is safe. __threadfence() (gpu scope) emits CCTL.IVALL -> flushes this
// SM's L1D, making other blocks' global writes visible after the barrier.
__device__ __forceinline__ void spinbar(unsigned target) {
    __syncthreads();
    if (threadIdx.x == 0) {
        __threadfence();                 // release: drain my stores
        atomicAdd(&g_ctr, 1u);
        while (*(volatile unsigned*)&g_ctr < target) { }
        __threadfence();                 // acquire + L1 invalidate
    }
    __syncthreads();
}

// ---------------- init: zero hidden ping-pong + zero buffer + barrier ctr --------
__global__ void initZero() {
    int idx = blockIdx.x * blockDim.x + threadIdx.x;
    if (idx == 0) g_ctr = 0u;
    const int nh = 3 * 2 * H_ * B_;   // 196608
    if (idx < nh) {
        (&g_h[0][0][0])[idx] = 0.0f;
    } else if (idx - nh < H_ * B_) {
        g_zero[idx - nh] = 0.0f;
    }
}

// ---------------- transpose x (B,S,I) -> paired [s][P(i,b)] ----------------------
__global__ void transposeX(const float* __restrict__ x) {
    int s = blockIdx.x;
    for (int d = threadIdx.x; d < I_ * B_; d += blockDim.x) {
        int i = ((d >> 6) << 1) + (d & 1);
        int b = (d & 63) >> 1;
        g_xP[s * (I_ * B_) + d] = x[b * (S_ * I_) + s * I_ + i];
    }
}

// ---------------- persistent GRU kernel ------------------------------------------
// Wavefront stages tau = 0..513: layer l processes t = tau - l.
// Phase A (576 jobs): pre_z, pre_r (h-side + in-side), g x-side.
// Phase B (192 jobs): g h-side ((r*h) @ Whg^T) + blend -> new h.
__global__ void __launch_bounds__(TPB, 1) gruPersist(
    const float* __restrict__ Wxz0, const float* __restrict__ Whz0, const float* __restrict__ bz0,
    const float* __restrict__ Wxr0, const float* __restrict__ Whr0, const float* __restrict__ br0,
    const float* __restrict__ Wxg0, const float* __restrict__ Whg0, const float* __restrict__ bg0,
    const float* __restrict__ Wxz,  const float* __restrict__ Whz,  const float* __restrict__ bz,
    const float* __restrict__ Wxr,  const float* __restrict__ Whr,  const float* __restrict__ br,
    const float* __restrict__ Wxg,  const float* __restrict__ Whg,  const float* __restrict__ bg)
{
    __shared__ float sm[16][16][32];
    const int w = threadIdx.x >> 5, lane = threadIdx.x & 31;
    unsigned barn = 0;

    for (int tau = 0; tau < S_ + 2; tau++) {
        // ================= phase A =================
        for (int job = blockIdx.x; job < 576; job += GRID) {
            int l, j0, isG;
            if (job < 384) { l = job % 3; j0 = (job / 3) << 3; isG = 0; }
            else { int q = job - 384; l = q % 3; j0 = (q / 3) << 4; isG = 1; }
            int t = tau - l;
            if (t < 0 || t >= S_) continue;

            const float* inP;
            int Kin;
            if (l == 0) { inP = g_xP + t * (I_ * B_); Kin = I_; }
            else        { inP = g_h[l - 1][(tau + 1) & 1]; Kin = H_; }
            const u64* in64 = (const u64*)inP;

            if (!isG) {
                // ---- z + r job: 8-j tile, gates swept sequentially ----
                const float *Wh_z, *Wx_z, *Wh_r, *Wx_r, *bzp, *brp;
                if (l == 0) { Wh_z = Whz0; Wx_z = Wxz0; Wh_r = Whr0; Wx_r = Wxr0; bzp = bz0; brp = br0; }
                else {
                    int wo = (l - 1) * H_ * H_, bo = (l - 1) * H_;
                    Wh_z = Whz + wo; Wx_z = Wxz + wo; Wh_r = Whr + wo; Wx_r = Wxr + wo;
                    bzp = bz + bo; brp = br + bo;
                }
                const float* hP = (l == 2) ? (t ? g_h2[t - 1] : g_zero) : g_h[l][(tau + 1) & 1];
                const u64* h64 = (const u64*)hP;

                u64 acc[8];
                const int npw = Kin >> 5;        // in-side pairs per warp
                const int pbh = w * 32;          // h-side pair base
                const int pbx = w * npw;         // in-side pair base

                // ---- gate Z ----
#pragma unroll
                for (int jj = 0; jj < 8; jj++) acc[jj] = 0ULL;
#pragma unroll 2
                for (int p = pbh; p < pbh + 32; p += 2) {
                    u64 a0 = h64[p * 32 + lane];
                    u64 a1 = h64[p * 32 + 32 + lane];
#pragma unroll
                    for (int jj = 0; jj < 8; jj++) {
                        ulonglong2 wv = *(const ulonglong2*)(Wh_z + (j0 + jj) * H_ + p * 2);
                        acc[jj] = fma2(wv.x, a0, acc[jj]);
                        acc[jj] = fma2(wv.y, a1, acc[jj]);
                    }
                }
#pragma unroll 2
                for (int p = pbx; p < pbx + npw; p += 2) {
                    u64 a0 = in64[p * 32 + lane];
                    u64 a1 = in64[p * 32 + 32 + lane];
#pragma unroll
                    for (int jj = 0; jj < 8; jj++) {
                        ulonglong2 wv = *(const ulonglong2*)(Wx_z + (j0 + jj) * Kin + p * 2);
                        acc[jj] = fma2(wv.x, a0, acc[jj]);
                        acc[jj] = fma2(wv.y, a1, acc[jj]);
                    }
                }
#pragma unroll
                for (int jj = 0; jj < 8; jj++) sm[w][jj][lane] = pairsum(acc[jj]);

                // ---- gate R ----
#pragma unroll
                for (int jj = 0; jj < 8; jj++) acc[jj] = 0ULL;
#pragma unroll 2
                for (int p = pbh; p < pbh + 32; p += 2) {
                    u64 a0 = h64[p * 32 + lane];
                    u64 a1 = h64[p * 32 + 32 + lane];
#pragma unroll
                    for (int jj = 0; jj < 8; jj++) {
                        ulonglong2 wv = *(const ulonglong2*)(Wh_r + (j0 + jj) * H_ + p * 2);
                        acc[jj] = fma2(wv.x, a0, acc[jj]);
                        acc[jj] = fma2(wv.y, a1, acc[jj]);
                    }
                }
#pragma unroll 2
                for (int p = pbx; p < pbx + npw; p += 2) {
                    u64 a0 = in64[p * 32 + lane];
                    u64 a1 = in64[p * 32 + 32 + lane];
#pragma unroll
                    for (int jj = 0; jj < 8; jj++) {
                        ulonglong2 wv = *(const ulonglong2*)(Wx_r + (j0 + jj) * Kin + p * 2);
                        acc[jj] = fma2(wv.x, a0, acc[jj]);
                        acc[jj] = fma2(wv.y, a1, acc[jj]);
                    }
                }
#pragma unroll
                for (int jj = 0; jj < 8; jj++) sm[w][8 + jj][lane] = pairsum(acc[jj]);

                __syncthreads();
                {   // warp w finalizes slot w: w<8 -> z (jj=w), w>=8 -> r (jj=w-8)
                    int jj = w & 7, gate = w >> 3;
                    int j = j0 + jj;
                    float s = gate ? brp[j] : bzp[j];
#pragma unroll
                    for (int q = 0; q < 16; q++) s += sm[q][w][lane];
                    int pidx = ((j >> 1) << 6) + (lane << 1) + (j & 1);
                    if (gate) g_r[l][pidx] = sigm(s);
                    else      g_z[l][pidx] = sigm(s);
                }
                __syncthreads();
            } else {
                // ---- g x-side job: 16-j tile ----
                const float *Wx_g, *bgp;
                if (l == 0) { Wx_g = Wxg0; bgp = bg0; }
                else { Wx_g = Wxg + (l - 1) * H_ * H_; bgp = bg + (l - 1) * H_; }

                u64 acc[16];
#pragma unroll
                for (int jj = 0; jj < 16; jj++) acc[jj] = 0ULL;
                const int npw = Kin >> 5;
                const int pbx = w * npw;
#pragma unroll 1
                for (int p = pbx; p < pbx + npw; p += 2) {
                    u64 a0 = in64[p * 32 + lane];
                    u64 a1 = in64[p * 32 + 32 + lane];
#pragma unroll
                    for (int jj = 0; jj < 16; jj++) {
                        ulonglong2 wv = *(const ulonglong2*)(Wx_g + (j0 + jj) * Kin + p * 2);
                        acc[jj] = fma2(wv.x, a0, acc[jj]);
                        acc[jj] = fma2(wv.y, a1, acc[jj]);
                    }
                }
#pragma unroll
                for (int jj = 0; jj < 16; jj++) sm[w][jj][lane] = pairsum(acc[jj]);
                __syncthreads();
                {
                    int j = j0 + w;
                    float s = bgp[j];
#pragma unroll
                    for (int q = 0; q < 16; q++) s += sm[q][w][lane];
                    g_gx[l][j * 32 + lane] = s;
                }
                __syncthreads();
            }
        }
        barn++; spinbar(barn * GRID);

        // ================= phase B =================
        for (int job = blockIdx.x; job < 192; job += GRID) {
            int l = job % 3, j0 = (job / 3) << 4;
            int t = tau - l;
            if (t < 0 || t >= S_) continue;

            const float* Wh_g = l ? (Whg + (l - 1) * H_ * H_) : Whg0;
            const float* hP = (l == 2) ? (t ? g_h2[t - 1] : g_zero) : g_h[l][(tau + 1) & 1];
            const u64* h64 = (const u64*)hP;
            const u64* r64 = (const u64*)&g_r[l][0];

            u64 acc[16];
#pragma unroll
            for (int jj = 0; jj < 16; jj++) acc[jj] = 0ULL;
            const int pb = w * 32;
#pragma unroll 1
            for (int p = pb; p < pb + 32; p += 2) {
                u64 rh0 = mul2(r64[p * 32 + lane], h64[p * 32 + lane]);
                u64 rh1 = mul2(r64[p * 32 + 32 + lane], h64[p * 32 + 32 + lane]);
#pragma unroll
                for (int jj = 0; jj < 16; jj++) {
                    ulonglong2 wv = *(const ulonglong2*)(Wh_g + (j0 + jj) * H_ + p * 2);
                    acc[jj] = fma2(wv.x, rh0, acc[jj]);
                    acc[jj] = fma2(wv.y, rh1, acc[jj]);
                }
            }
#pragma unroll
            for (int jj = 0; jj < 16; jj++) sm[w][jj][lane] = pairsum(acc[jj]);
            __syncthreads();
            {
                int j = j0 + w;
                float s = 0.0f;
#pragma unroll
                for (int q = 0; q < 16; q++) s += sm[q][w][lane];
                float gv = tanhf(g_gx[l][j * 32 + lane] + s);
                int pidx = ((j >> 1) << 6) + (lane << 1) + (j & 1);
                float zv = g_z[l][pidx];
                float hold = hP[pidx];
                float hn = zv * hold + (1.0f - zv) * gv;
                float* hout = (l == 2) ? g_h2[t] : g_h[l][tau & 1];
                hout[pidx] = hn;
            }
            __syncthreads();
        }
        barn++; spinbar(barn * GRID);
    }
}

// ---------------- output head: out[b][s][o] = h2[s] . Wout[o] + bout[o] ----------
__global__ void __launch_bounds__(256) outHead(
    const float* __restrict__ Wout, const float* __restrict__ bout,
    float* __restrict__ out)
{
    int s = blockIdx.x;
    int w = threadIdx.x >> 5, lane = threadIdx.x & 31;  // lane = batch
    const u64* h64 = (const u64*)g_h2[s];
    int o0 = w * 16;

    u64 acc[16];
#pragma unroll
    for (int oo = 0; oo < 16; oo++) acc[oo] = 0ULL;
#pragma unroll 1
    for (int p = 0; p < 512; p += 2) {
        u64 a0 = h64[p * 32 + lane];
        u64 a1 = h64[p * 32 + 32 + lane];
#pragma unroll
        for (int oo = 0; oo < 16; oo++) {
            ulonglong2 wv = *(const ulonglong2*)(Wout + (o0 + oo) * H_ + p * 2);
            acc[oo] = fma2(wv.x, a0, acc[oo]);
            acc[oo] = fma2(wv.y, a1, acc[oo]);
        }
    }
#pragma unroll
    for (int oo = 0; oo < 16; oo++) {
        int o = o0 + oo;
        out[lane * (S_ * O_) + s * O_ + o] = pairsum(acc[oo]) + bout[o];
    }
}

// ---------------- final hidden state: out2[b][l][j] -------------------------------
__global__ void finalH(float* __restrict__ out) {
    int idx = blockIdx.x * blockDim.x + threadIdx.x;
    if (idx >= 3 * H_ * B_) return;
    int b = idx & 31;
    int j = (idx >> 5) & (H_ - 1);
    int l = idx >> 15;
    const float* src = (l == 2) ? g_h2[S_ - 1] : g_h[l][(S_ - 1 + l) & 1];
    int pidx = ((j >> 1) << 6) + (b << 1) + (j & 1);
    out[B_ * S_ * O_ + b * (3 * H_) + l * H_ + j] = src[pidx];
}

// ---------------- host ------------------------------------------------------------
extern "C" void kernel_launch(void* const* d_in, const int* in_sizes, int n_in,
                              void* d_out, int out_size) {
    const float* x    = (const float*)d_in[0];
    const float* Wxz0 = (const float*)d_in[1];
    const float* Whz0 = (const float*)d_in[2];
    const float* bz0  = (const float*)d_in[3];
    const float* Wxr0 = (const float*)d_in[4];
    const float* Whr0 = (const float*)d_in[5];
    const float* br0  = (const float*)d_in[6];
    const float* Wxg0 = (const float*)d_in[7];
    const float* Whg0 = (const float*)d_in[8];
    const float* bg0  = (const float*)d_in[9];
    const float* Wxz  = (const float*)d_in[10];
    const float* Whz  = (const float*)d_in[11];
    const float* bz   = (const float*)d_in[12];
    const float* Wxr  = (const float*)d_in[13];
    const float* Whr  = (const float*)d_in[14];
    const float* br   = (const float*)d_in[15];
    const float* Wxg  = (const float*)d_in[16];
    const float* Whg  = (const float*)d_in[17];
    const float* bg   = (const float*)d_in[18];
    const float* Wout = (const float*)d_in[19];
    const float* bout = (const float*)d_in[20];
    float* out = (float*)d_out;

    initZero<<<(3 * 2 * H_ * B_ + H_ * B_ + 255) / 256, 256>>>();
    transposeX<<<S_, 256>>>(x);

    gruPersist<<<GRID, TPB>>>(
        Wxz0, Whz0, bz0, Wxr0, Whr0, br0, Wxg0, Whg0, bg0,
        Wxz, Whz, bz, Wxr, Whr, br, Wxg, Whg, bg);

    outHead<<<S_, 256>>>(Wout, bout, out);
    finalH<<<(3 * H_ * B_ + 255) / 256, 256>>>(out);
}

// round 15
// speedup vs baseline: 1.0005x; 1.0005x over previous
#include <cuda_runtime.h>
#include <math.h>

#define S_  512
#define B_  32
#define I_  128
#define H_  1024
#define O_  128
#define GRID 148
#define TPB  512

typedef unsigned long long u64;

// ---------------- device scratch (static globals; no allocation) ----------------
// Paired activation layout P(k,b): float offset (k>>1)*64 + b*2 + (k&1).
// As u64 array: pair p (k=2p,2p+1) for batch b lives at u64 index p*32 + b.
__device__ __align__(16) float g_xP[S_ * I_ * B_];   // x per timestep, P layout
__device__ __align__(16) float g_h[3][2][H_ * B_];   // ping-pong hidden (P layout)
__device__ __align__(16) float g_z[3][H_ * B_];      // z gate (P layout)
__device__ __align__(16) float g_r[3][H_ * B_];      // r gate (P layout)
__device__ __align__(16) float g_gx[3][H_ * B_];     // g x-side pre-act + bias: [j*32+b]
__device__ __align__(16) float g_h2[S_][H_ * B_];    // layer-2 hidden history (P layout)
__device__ __align__(16) float g_zero[H_ * B_];      // zeros (layer-2 t=0)
__device__ unsigned g_ctr;                           // grid barrier counter

// ---------------- packed fp32x2 helpers ------------------------------------------
__device__ __forceinline__ u64 fma2(u64 a, u64 b, u64 c) {
    u64 d;
    asm("fma.rn.f32x2 %0, %1, %2, %3;" : "=l"(d) : "l"(a), "l"(b), "l"(c));
    return d;
}
__device__ __forceinline__ u64 mul2(u64 a, u64 b) {
    u64 d;
    asm("mul.rn.f32x2 %0, %1, %2;" : "=l"(d) : "l"(a), "l"(b));
    return d;
}
__device__ __forceinline__ float pairsum(u64 v) {
    float lo, hi;
    asm("mov.b64 {%0, %1}, %2;" : "=f"(lo), "=f"(hi) : "l"(v));
    return lo + hi;
}
__device__ __forceinline__ float sigm(float x) { return 1.0f / (1.0f + expf(-x)); }

// ---------------- software grid barrier ------------------------------------------
// All 148 blocks are co-resident (1 block/SM via launch_bounds + 32KB smem), so
// spinning is safe. __threadfence() (gpu scope) emits CCTL.IVALL -> flushes this
// SM's L1D, making other blocks' global writes visible after the barrier.
__device__ __forceinline__ void spinbar(unsigned target) {
    __syncthreads();
    if (threadIdx.x == 0) {
        __threadfence();                 // release: drain my stores
        atomicAdd(&g_ctr, 1u);
        while (*(volatile unsigned*)&g_ctr < target) { }
        __threadfence();                 // acquire + L1 invalidate
    }
    __syncthreads();
}

// ---------------- init: zero hidden ping-pong + zero buffer + barrier ctr --------
__global__ void initZero() {
    int idx = blockIdx.x * blockDim.x + threadIdx.x;
    if (idx == 0) g_ctr = 0u;
    const int nh = 3 * 2 * H_ * B_;   // 196608
    if (idx < nh) {
        (&g_h[0][0][0])[idx] = 0.0f;
    } else if (idx - nh < H_ * B_) {
        g_zero[idx - nh] = 0.0f;
    }
}

// ---------------- transpose x (B,S,I) -> paired [s][P(i,b)] ----------------------
__global__ void transposeX(const float* __restrict__ x) {
    int s = blockIdx.x;
    for (int d = threadIdx.x; d < I_ * B_; d += blockDim.x) {
        int i = ((d >> 6) << 1) + (d & 1);
        int b = (d & 63) >> 1;
        g_xP[s * (I_ * B_) + d] = x[b * (S_ * I_) + s * I_ + i];
    }
}

// ---------------- persistent GRU kernel ------------------------------------------
// Wavefront stages tau = 0..513: layer l processes t = tau - l.
// Phase A (576 jobs): pre_z, pre_r (h-side + in-side), g x-side.
// Phase B (192 jobs): g h-side ((r*h) @ Whg^T) + blend -> new h.
__global__ void __launch_bounds__(TPB, 1) gruPersist(
    const float* __restrict__ Wxz0, const float* __restrict__ Whz0, const float* __restrict__ bz0,
    const float* __restrict__ Wxr0, const float* __restrict__ Whr0, const float* __restrict__ br0,
    const float* __restrict__ Wxg0, const float* __restrict__ Whg0, const float* __restrict__ bg0,
    const float* __restrict__ Wxz,  const float* __restrict__ Whz,  const float* __restrict__ bz,
    const float* __restrict__ Wxr,  const float* __restrict__ Whr,  const float* __restrict__ br,
    const float* __restrict__ Wxg,  const float* __restrict__ Whg,  const float* __restrict__ bg)
{
    __shared__ float sm[16][16][32];
    const int w = threadIdx.x >> 5, lane = threadIdx.x & 31;
    unsigned barn = 0;

    for (int tau = 0; tau < S_ + 2; tau++) {
        // ================= phase A =================
        for (int job = blockIdx.x; job < 576; job += GRID) {
            int l, j0, isG;
            if (job < 384) { l = job % 3; j0 = (job / 3) << 3; isG = 0; }
            else { int q = job - 384; l = q % 3; j0 = (q / 3) << 4; isG = 1; }
            int t = tau - l;
            if (t < 0 || t >= S_) continue;

            const float* inP;
            int Kin;
            if (l == 0) { inP = g_xP + t * (I_ * B_); Kin = I_; }
            else        { inP = g_h[l - 1][(tau + 1) & 1]; Kin = H_; }
            const u64* in64 = (const u64*)inP;

            if (!isG) {
                // ---- z + r job: 8-j tile, gates swept sequentially ----
                const float *Wh_z, *Wx_z, *Wh_r, *Wx_r, *bzp, *brp;
                if (l == 0) { Wh_z = Whz0; Wx_z = Wxz0; Wh_r = Whr0; Wx_r = Wxr0; bzp = bz0; brp = br0; }
                else {
                    int wo = (l - 1) * H_ * H_, bo = (l - 1) * H_;
                    Wh_z = Whz + wo; Wx_z = Wxz + wo; Wh_r = Whr + wo; Wx_r = Wxr + wo;
                    bzp = bz + bo; brp = br + bo;
                }
                const float* hP = (l == 2) ? (t ? g_h2[t - 1] : g_zero) : g_h[l][(tau + 1) & 1];
                const u64* h64 = (const u64*)hP;

                u64 acc[8];
                const int npw = Kin >> 5;        // in-side pairs per warp
                const int pbh = w * 32;          // h-side pair base
                const int pbx = w * npw;         // in-side pair base

                // ---- gate Z ----
#pragma unroll
                for (int jj = 0; jj < 8; jj++) acc[jj] = 0ULL;
#pragma unroll 2
                for (int p = pbh; p < pbh + 32; p += 2) {
                    u64 a0 = h64[p * 32 + lane];
                    u64 a1 = h64[p * 32 + 32 + lane];
#pragma unroll
                    for (int jj = 0; jj < 8; jj++) {
                        ulonglong2 wv = *(const ulonglong2*)(Wh_z + (j0 + jj) * H_ + p * 2);
                        acc[jj] = fma2(wv.x, a0, acc[jj]);
                        acc[jj] = fma2(wv.y, a1, acc[jj]);
                    }
                }
#pragma unroll 2
                for (int p = pbx; p < pbx + npw; p += 2) {
                    u64 a0 = in64[p * 32 + lane];
                    u64 a1 = in64[p * 32 + 32 + lane];
#pragma unroll
                    for (int jj = 0; jj < 8; jj++) {
                        ulonglong2 wv = *(const ulonglong2*)(Wx_z + (j0 + jj) * Kin + p * 2);
                        acc[jj] = fma2(wv.x, a0, acc[jj]);
                        acc[jj] = fma2(wv.y, a1, acc[jj]);
                    }
                }
#pragma unroll
                for (int jj = 0; jj < 8; jj++) sm[w][jj][lane] = pairsum(acc[jj]);

                // ---- gate R ----
#pragma unroll
                for (int jj = 0; jj < 8; jj++) acc[jj] = 0ULL;
#pragma unroll 2
                for (int p = pbh; p < pbh + 32; p += 2) {
                    u64 a0 = h64[p * 32 + lane];
                    u64 a1 = h64[p * 32 + 32 + lane];
#pragma unroll
                    for (int jj = 0; jj < 8; jj++) {
                        ulonglong2 wv = *(const ulonglong2*)(Wh_r + (j0 + jj) * H_ + p * 2);
                        acc[jj] = fma2(wv.x, a0, acc[jj]);
                        acc[jj] = fma2(wv.y, a1, acc[jj]);
                    }
                }
#pragma unroll 2
                for (int p = pbx; p < pbx + npw; p += 2) {
                    u64 a0 = in64[p * 32 + lane];
                    u64 a1 = in64[p * 32 + 32 + lane];
#pragma unroll
                    for (int jj = 0; jj < 8; jj++) {
                        ulonglong2 wv = *(const ulonglong2*)(Wx_r + (j0 + jj) * Kin + p * 2);
                        acc[jj] = fma2(wv.x, a0, acc[jj]);
                        acc[jj] = fma2(wv.y, a1, acc[jj]);
                    }
                }
#pragma unroll
                for (int jj = 0; jj < 8; jj++) sm[w][8 + jj][lane] = pairsum(acc[jj]);

                __syncthreads();
                {   // warp w finalizes slot w: w<8 -> z (jj=w), w>=8 -> r (jj=w-8)
                    int jj = w & 7, gate = w >> 3;
                    int j = j0 + jj;
                    float s = gate ? brp[j] : bzp[j];
#pragma unroll
                    for (int q = 0; q < 16; q++) s += sm[q][w][lane];
                    int pidx = ((j >> 1) << 6) + (lane << 1) + (j & 1);
                    if (gate) g_r[l][pidx] = sigm(s);
                    else      g_z[l][pidx] = sigm(s);
                }
                __syncthreads();
            } else {
                // ---- g x-side job: 16-j tile ----
                const float *Wx_g, *bgp;
                if (l == 0) { Wx_g = Wxg0; bgp = bg0; }
                else { Wx_g = Wxg + (l - 1) * H_ * H_; bgp = bg + (l - 1) * H_; }

                u64 acc[16];
#pragma unroll
                for (int jj = 0; jj < 16; jj++) acc[jj] = 0ULL;
                const int npw = Kin >> 5;
                const int pbx = w * npw;
#pragma unroll 1
                for (int p = pbx; p < pbx + npw; p += 2) {
                    u64 a0 = in64[p * 32 + lane];
                    u64 a1 = in64[p * 32 + 32 + lane];
#pragma unroll
                    for (int jj = 0; jj < 16; jj++) {
                        ulonglong2 wv = *(const ulonglong2*)(Wx_g + (j0 + jj) * Kin + p * 2);
                        acc[jj] = fma2(wv.x, a0, acc[jj]);
                        acc[jj] = fma2(wv.y, a1, acc[jj]);
                    }
                }
#pragma unroll
                for (int jj = 0; jj < 16; jj++) sm[w][jj][lane] = pairsum(acc[jj]);
                __syncthreads();
                {
                    int j = j0 + w;
                    float s = bgp[j];
#pragma unroll
                    for (int q = 0; q < 16; q++) s += sm[q][w][lane];
                    g_gx[l][j * 32 + lane] = s;
                }
                __syncthreads();
            }
        }
        barn++; spinbar(barn * GRID);

        // ================= phase B =================
        for (int job = blockIdx.x; job < 192; job += GRID) {
            int l = job % 3, j0 = (job / 3) << 4;
            int t = tau - l;
            if (t < 0 || t >= S_) continue;

            const float* Wh_g = l ? (Whg + (l - 1) * H_ * H_) : Whg0;
            const float* hP = (l == 2) ? (t ? g_h2[t - 1] : g_zero) : g_h[l][(tau + 1) & 1];
            const u64* h64 = (const u64*)hP;
            const u64* r64 = (const u64*)&g_r[l][0];

            u64 acc[16];
#pragma unroll
            for (int jj = 0; jj < 16; jj++) acc[jj] = 0ULL;
            const int pb = w * 32;
#pragma unroll 1
            for (int p = pb; p < pb + 32; p += 2) {
                u64 rh0 = mul2(r64[p * 32 + lane], h64[p * 32 + lane]);
                u64 rh1 = mul2(r64[p * 32 + 32 + lane], h64[p * 32 + 32 + lane]);
#pragma unroll
                for (int jj = 0; jj < 16; jj++) {
                    ulonglong2 wv = *(const ulonglong2*)(Wh_g + (j0 + jj) * H_ + p * 2);
                    acc[jj] = fma2(wv.x, rh0, acc[jj]);
                    acc[jj] = fma2(wv.y, rh1, acc[jj]);
                }
            }
#pragma unroll
            for (int jj = 0; jj < 16; jj++) sm[w][jj][lane] = pairsum(acc[jj]);
            __syncthreads();
            {
                int j = j0 + w;
                float s = 0.0f;
#pragma unroll
                for (int q = 0; q < 16; q++) s += sm[q][w][lane];
                float gv = tanhf(g_gx[l][j * 32 + lane] + s);
                int pidx = ((j >> 1) << 6) + (lane << 1) + (j & 1);
                float zv = g_z[l][pidx];
                float hold = hP[pidx];
                float hn = zv * hold + (1.0f - zv) * gv;
                float* hout = (l == 2) ? g_h2[t] : g_h[l][tau & 1];
                hout[pidx] = hn;
            }
            __syncthreads();
        }
        barn++; spinbar(barn * GRID);
    }
}

// ---------------- output head: out[b][s][o] = h2[s] . Wout[o] + bout[o] ----------
__global__ void __launch_bounds__(256) outHead(
    const float* __restrict__ Wout, const float* __restrict__ bout,
    float* __restrict__ out)
{
    int s = blockIdx.x;
    int w = threadIdx.x >> 5, lane = threadIdx.x & 31;  // lane = batch
    const u64* h64 = (const u64*)g_h2[s];
    int o0 = w * 16;

    u64 acc[16];
#pragma unroll
    for (int oo = 0; oo < 16; oo++) acc[oo] = 0ULL;
#pragma unroll 1
    for (int p = 0; p < 512; p += 2) {
        u64 a0 = h64[p * 32 + lane];
        u64 a1 = h64[p * 32 + 32 + lane];
#pragma unroll
        for (int oo = 0; oo < 16; oo++) {
            ulonglong2 wv = *(const ulonglong2*)(Wout + (o0 + oo) * H_ + p * 2);
            acc[oo] = fma2(wv.x, a0, acc[oo]);
            acc[oo] = fma2(wv.y, a1, acc[oo]);
        }
    }
#pragma unroll
    for (int oo = 0; oo < 16; oo++) {
        int o = o0 + oo;
        out[lane * (S_ * O_) + s * O_ + o] = pairsum(acc[oo]) + bout[o];
    }
}

// ---------------- final hidden state: out2[b][l][j] -------------------------------
__global__ void finalH(float* __restrict__ out) {
    int idx = blockIdx.x * blockDim.x + threadIdx.x;
    if (idx >= 3 * H_ * B_) return;
    int b = idx & 31;
    int j = (idx >> 5) & (H_ - 1);
    int l = idx >> 15;
    const float* src = (l == 2) ? g_h2[S_ - 1] : g_h[l][(S_ - 1 + l) & 1];
    int pidx = ((j >> 1) << 6) + (b << 1) + (j & 1);
    out[B_ * S_ * O_ + b * (3 * H_) + l * H_ + j] = src[pidx];
}

// ---------------- host ------------------------------------------------------------
extern "C" void kernel_launch(void* const* d_in, const int* in_sizes, int n_in,
                              void* d_out, int out_size) {
    const float* x    = (const float*)d_in[0];
    const float* Wxz0 = (const float*)d_in[1];
    const float* Whz0 = (const float*)d_in[2];
    const float* bz0  = (const float*)d_in[3];
    const float* Wxr0 = (const float*)d_in[4];
    const float* Whr0 = (const float*)d_in[5];
    const float* br0  = (const float*)d_in[6];
    const float* Wxg0 = (const float*)d_in[7];
    const float* Whg0 = (const float*)d_in[8];
    const float* bg0  = (const float*)d_in[9];
    const float* Wxz  = (const float*)d_in[10];
    const float* Whz  = (const float*)d_in[11];
    const float* bz   = (const float*)d_in[12];
    const float* Wxr  = (const float*)d_in[13];
    const float* Whr  = (const float*)d_in[14];
    const float* br   = (const float*)d_in[15];
    const float* Wxg  = (const float*)d_in[16];
    const float* Whg  = (const float*)d_in[17];
    const float* bg   = (const float*)d_in[18];
    const float* Wout = (const float*)d_in[19];
    const float* bout = (const float*)d_in[20];
    float* out = (float*)d_out;

    initZero<<<(3 * 2 * H_ * B_ + H_ * B_ + 255) / 256, 256>>>();
    transposeX<<<S_, 256>>>(x);

    gruPersist<<<GRID, TPB>>>(
        Wxz0, Whz0, bz0, Wxr0, Whr0, br0, Wxg0, Whg0, bg0,
        Wxz, Whz, bz, Wxr, Whr, br, Wxg, Whg, bg);

    outHead<<<S_, 256>>>(Wout, bout, out);
    finalH<<<(3 * H_ * B_ + 255) / 256, 256>>>(out);
}

// round 16
// speedup vs baseline: 1.3033x; 1.3026x over previous
#include <cuda_runtime.h>
#include <math.h>

#define S_  512
#define B_  32
#define I_  128
#define H_  1024
#define O_  128
#define GRID 148
#define TPB  512
#define NWARP (GRID * (TPB / 32))

typedef unsigned long long u64;

// ---------------- device scratch (b-major [B][K] everywhere) ---------------------
__device__ __align__(16) float g_h[3][2][B_ * H_];   // ping-pong hidden per layer
__device__ __align__(16) float g_z[3][B_ * H_];      // z gate
__device__ __align__(16) float g_r[3][B_ * H_];      // r gate
__device__ __align__(16) float g_gx[3][B_ * H_];     // g x-side pre-act + bias
__device__ __align__(16) float g_h2[S_][B_ * H_];    // layer-2 hidden history
__device__ __align__(16) float g_hz[B_ * H_];        // zeros (layer-2 t=0)
__device__ unsigned g_ctr;                           // grid barrier counter

// ---------------- packed fp32x2 helpers ------------------------------------------
__device__ __forceinline__ u64 fma2(u64 a, u64 b, u64 c) {
    u64 d;
    asm("fma.rn.f32x2 %0, %1, %2, %3;" : "=l"(d) : "l"(a), "l"(b), "l"(c));
    return d;
}
__device__ __forceinline__ u64 mul2(u64 a, u64 b) {
    u64 d;
    asm("mul.rn.f32x2 %0, %1, %2;" : "=l"(d) : "l"(a), "l"(b));
    return d;
}
__device__ __forceinline__ float pairsum(u64 v) {
    float lo, hi;
    asm("mov.b64 {%0, %1}, %2;" : "=f"(lo), "=f"(hi) : "l"(v));
    return lo + hi;
}
__device__ __forceinline__ float sigm(float x) { return 1.0f / (1.0f + expf(-x)); }

// ---------------- warp GEMM segment: k-in-lanes, tile J=4 x Bt=8 ------------------
// acc[jj*8+bb] += sum_k W[jj][k] * act[bb][k] (k split over lanes, 4 f32/lane/iter).
// All loads per-lane-distinct coalesced LDG.128. 12 LDG per 64 FFMA2.
template<bool RM>
__device__ __forceinline__ void segAcc(u64* acc,
    const float* __restrict__ wb, int ws,   // weight rows base (row j0), stride
    const float* __restrict__ ab, int as,   // act rows base (row b0), stride
    const float* __restrict__ rb,           // r rows (stride as) when RM
    int klen, int lane)
{
    int off = lane << 2;
    const int nIt = klen >> 7;
#pragma unroll 1
    for (int i = 0; i < nIt; i++, off += 128) {
        ulonglong2 w0 = *(const ulonglong2*)(wb + 0 * ws + off);
        ulonglong2 w1 = *(const ulonglong2*)(wb + 1 * ws + off);
        ulonglong2 w2 = *(const ulonglong2*)(wb + 2 * ws + off);
        ulonglong2 w3 = *(const ulonglong2*)(wb + 3 * ws + off);
#pragma unroll
        for (int bb = 0; bb < 8; bb++) {
            ulonglong2 a = *(const ulonglong2*)(ab + bb * as + off);
            if (RM) {
                ulonglong2 rv = *(const ulonglong2*)(rb + bb * as + off);
                a.x = mul2(rv.x, a.x);
                a.y = mul2(rv.y, a.y);
            }
            acc[0 * 8 + bb] = fma2(w0.x, a.x, acc[0 * 8 + bb]);
            acc[0 * 8 + bb] = fma2(w0.y, a.y, acc[0 * 8 + bb]);
            acc[1 * 8 + bb] = fma2(w1.x, a.x, acc[1 * 8 + bb]);
            acc[1 * 8 + bb] = fma2(w1.y, a.y, acc[1 * 8 + bb]);
            acc[2 * 8 + bb] = fma2(w2.x, a.x, acc[2 * 8 + bb]);
            acc[2 * 8 + bb] = fma2(w2.y, a.y, acc[2 * 8 + bb]);
            acc[3 * 8 + bb] = fma2(w3.x, a.x, acc[3 * 8 + bb]);
            acc[3 * 8 + bb] = fma2(w3.y, a.y, acc[3 * 8 + bb]);
        }
    }
}

// ---------------- cross-lane reduce: 32 values -> lane L owns total of value L ----
__device__ __forceinline__ float reduce32(u64* acc, int lane) {
    float v[32];
#pragma unroll
    for (int i = 0; i < 32; i++) v[i] = pairsum(acc[i]);
#pragma unroll
    for (int off = 16; off >= 1; off >>= 1) {
        bool hi = (lane & off) != 0;
#pragma unroll
        for (int i = 0; i < 16; i++) {
            if (i >= off) break;
            float send = hi ? v[i] : v[i + off];
            float recv = __shfl_xor_sync(0xffffffffu, send, off);
            v[i] = (hi ? v[i + off] : v[i]) + recv;
        }
    }
    return v[0];
}

// ---------------- software grid barrier (1 block/SM guaranteed by full RF) --------
__device__ __forceinline__ void spinbar(unsigned target) {
    __syncthreads();
    if (threadIdx.x == 0) {
        __threadfence();                 // release (CCTL.IVALL)
        atomicAdd(&g_ctr, 1u);
        while (*(volatile unsigned*)&g_ctr < target) { }
        __threadfence();                 // acquire + L1D invalidate
    }
    __syncthreads();
}

// ---------------- init -------------------------------------------------------------
__global__ void initZero() {
    int idx = blockIdx.x * blockDim.x + threadIdx.x;
    if (idx == 0) g_ctr = 0u;
    const int nh = 3 * 2 * B_ * H_;
    if (idx < nh) (&g_h[0][0][0])[idx] = 0.0f;
    else if (idx - nh < B_ * H_) g_hz[idx - nh] = 0.0f;
}

// ---------------- persistent GRU kernel --------------------------------------------
// Wavefront: stage tau runs layer l at t = tau - l.
// Phase A: 9216 warp-tasks = 9 (l,gate) combos x 256 j-tiles x 4 b-tiles.
// Phase B: 3072 warp-tasks = 3 layers x 256 j-tiles x 4 b-tiles ((r*h)@Whg^T + blend).
__global__ void __launch_bounds__(TPB, 1) gruPersist(
    const float* __restrict__ x,
    const float* __restrict__ Wxz0, const float* __restrict__ Whz0, const float* __restrict__ bz0,
    const float* __restrict__ Wxr0, const float* __restrict__ Whr0, const float* __restrict__ br0,
    const float* __restrict__ Wxg0, const float* __restrict__ Whg0, const float* __restrict__ bg0,
    const float* __restrict__ Wxz,  const float* __restrict__ Whz,  const float* __restrict__ bz,
    const float* __restrict__ Wxr,  const float* __restrict__ Whr,  const float* __restrict__ br,
    const float* __restrict__ Wxg,  const float* __restrict__ Whg,  const float* __restrict__ bg)
{
    const int w = threadIdx.x >> 5, lane = threadIdx.x & 31;
    const int gw = blockIdx.x * (TPB / 32) + w;
    unsigned barn = 0;
    u64 acc[32];

    for (int tau = 0; tau < S_ + 2; tau++) {
        // ================= phase A: z, r, g-x pre-activations =================
        for (int task = gw; task < 9216; task += NWARP) {
            int c = task >> 10;              // 0..8
            int rem = task & 1023;
            int l = c / 3, gate = c % 3;     // 0=z 1=r 2=gx
            int t = tau - l;
            if (t < 0 || t >= S_) continue;
            int j0 = (rem >> 2) << 2;        // j-tile of 4
            int b0 = (rem & 3) << 3;         // b-tile of 8

            const float *Wx_p, *Wh_p, *bp;
            int Kin;
            const float* inA;
            int inS;
            if (l == 0) {
                Wx_p = (gate == 0) ? Wxz0 : (gate == 1) ? Wxr0 : Wxg0;
                Wh_p = (gate == 0) ? Whz0 : Whr0;
                bp   = (gate == 0) ? bz0  : (gate == 1) ? br0  : bg0;
                Kin = I_;
                inA = x + t * I_;  inS = S_ * I_;
            } else {
                int wo = (l - 1) * H_ * H_, bo = (l - 1) * H_;
                Wx_p = ((gate == 0) ? Wxz : (gate == 1) ? Wxr : Wxg) + wo;
                Wh_p = ((gate == 0) ? Whz : Whr) + wo;
                bp   = ((gate == 0) ? bz  : (gate == 1) ? br  : bg) + bo;
                Kin = H_;
                inA = g_h[l - 1][(tau + 1) & 1];  inS = H_;
            }

#pragma unroll
            for (int i = 0; i < 32; i++) acc[i] = 0ULL;
            segAcc<false>(acc, Wx_p + j0 * Kin, Kin, inA + b0 * inS, inS, 0, Kin, lane);
            if (gate < 2) {
                const float* hA = (l == 2) ? (t ? g_h2[t - 1] : g_hz)
                                           : g_h[l][(tau + 1) & 1];
                segAcc<false>(acc, Wh_p + j0 * H_, H_, hA + b0 * H_, H_, 0, H_, lane);
            }
            float s = reduce32(acc, lane);
            int j = j0 + (lane >> 3), b = b0 + (lane & 7);
            s += bp[j];
            if (gate == 0)      g_z[l][b * H_ + j] = sigm(s);
            else if (gate == 1) g_r[l][b * H_ + j] = sigm(s);
            else                g_gx[l][b * H_ + j] = s;
        }
        barn++; spinbar(barn * GRID);

        // ================= phase B: (r*h)@Whg^T + blend =================
        for (int task = gw; task < 3072; task += NWARP) {
            int l = task >> 10;
            int rem = task & 1023;
            int t = tau - l;
            if (t < 0 || t >= S_) continue;
            int j0 = (rem >> 2) << 2;
            int b0 = (rem & 3) << 3;

            const float* Wh_g = l ? (Whg + (l - 1) * H_ * H_) : Whg0;
            const float* hA = (l == 2) ? (t ? g_h2[t - 1] : g_hz)
                                       : g_h[l][(tau + 1) & 1];

#pragma unroll
            for (int i = 0; i < 32; i++) acc[i] = 0ULL;
            segAcc<true>(acc, Wh_g + j0 * H_, H_, hA + b0 * H_, H_,
                         &g_r[l][0] + b0 * H_, H_, lane);
            float s = reduce32(acc, lane);
            int j = j0 + (lane >> 3), b = b0 + (lane & 7);
            float gv = tanhf(g_gx[l][b * H_ + j] + s);
            float zv = g_z[l][b * H_ + j];
            float hold = hA[b * H_ + j];
            float hn = zv * hold + (1.0f - zv) * gv;
            float* hout = (l == 2) ? g_h2[t] : g_h[l][tau & 1];
            hout[b * H_ + j] = hn;
        }
        barn++; spinbar(barn * GRID);
    }
}

// ---------------- output head: out[b][s][o] = h2[s][b] . Wout[o] + bout[o] --------
__global__ void __launch_bounds__(256) outHead(
    const float* __restrict__ Wout, const float* __restrict__ bout,
    float* __restrict__ out)
{
    int s = blockIdx.x;
    int w = threadIdx.x >> 5, lane = threadIdx.x & 31;
    u64 acc[32];
    for (int tile = w; tile < 128; tile += 8) {   // 32 j-tiles x 4 b-tiles
        int j0 = (tile >> 2) << 2;
        int b0 = (tile & 3) << 3;
#pragma unroll
        for (int i = 0; i < 32; i++) acc[i] = 0ULL;
        segAcc<false>(acc, Wout + j0 * H_, H_, g_h2[s] + b0 * H_, H_, 0, H_, lane);
        float v = reduce32(acc, lane);
        int o = j0 + (lane >> 3), b = b0 + (lane & 7);
        out[b * (S_ * O_) + s * O_ + o] = v + bout[o];
    }
}

// ---------------- final hidden state: out2[b][l][j] --------------------------------
__global__ void finalH(float* __restrict__ out) {
    int idx = blockIdx.x * blockDim.x + threadIdx.x;
    if (idx >= 3 * H_ * B_) return;
    int b = idx & 31;
    int j = (idx >> 5) & (H_ - 1);
    int l = idx >> 15;
    const float* src = (l == 2) ? g_h2[S_ - 1] : g_h[l][(S_ - 1 + l) & 1];
    out[B_ * S_ * O_ + b * (3 * H_) + l * H_ + j] = src[b * H_ + j];
}

// ---------------- host ---------------------------------------------------------------
extern "C" void kernel_launch(void* const* d_in, const int* in_sizes, int n_in,
                              void* d_out, int out_size) {
    const float* x    = (const float*)d_in[0];
    const float* Wxz0 = (const float*)d_in[1];
    const float* Whz0 = (const float*)d_in[2];
    const float* bz0  = (const float*)d_in[3];
    const float* Wxr0 = (const float*)d_in[4];
    const float* Whr0 = (const float*)d_in[5];
    const float* br0  = (const float*)d_in[6];
    const float* Wxg0 = (const float*)d_in[7];
    const float* Whg0 = (const float*)d_in[8];
    const float* bg0  = (const float*)d_in[9];
    const float* Wxz  = (const float*)d_in[10];
    const float* Whz  = (const float*)d_in[11];
    const float* bz   = (const float*)d_in[12];
    const float* Wxr  = (const float*)d_in[13];
    const float* Whr  = (const float*)d_in[14];
    const float* br   = (const float*)d_in[15];
    const float* Wxg  = (const float*)d_in[16];
    const float* Whg  = (const float*)d_in[17];
    const float* bg   = (const float*)d_in[18];
    const float* Wout = (const float*)d_in[19];
    const float* bout = (const float*)d_in[20];
    float* out = (float*)d_out;

    initZero<<<(3 * 2 * B_ * H_ + B_ * H_ + 255) / 256, 256>>>();

    gruPersist<<<GRID, TPB>>>(x,
        Wxz0, Whz0, bz0, Wxr0, Whr0, br0, Wxg0, Whg0, bg0,
        Wxz, Whz, bz, Wxr, Whr, br, Wxg, Whg, bg);

    outHead<<<S_, 256>>>(Wout, bout, out);
    finalH<<<(3 * H_ * B_ + 255) / 256, 256>>>(out);
}

// round 17
// speedup vs baseline: 1.3946x; 1.0701x over previous
#include <cuda_runtime.h>
#include <math.h>

#define S_  512
#define B_  32
#define I_  128
#define H_  1024
#define O_  128
#define GRID 148
#define TPB  512

typedef unsigned long long u64;

// ---------------- device scratch (b-major [B][K] everywhere) ---------------------
__device__ __align__(16) float g_h[3][2][B_ * H_];   // ping-pong hidden per layer
__device__ __align__(16) float g_z[3][B_ * H_];      // z gate
__device__ __align__(16) float g_r[3][B_ * H_];      // r gate
__device__ __align__(16) float g_gx[3][B_ * H_];     // g x-side pre-act + bias
__device__ __align__(16) float g_h2[S_][B_ * H_];    // layer-2 hidden history
__device__ __align__(16) float g_hz[B_ * H_];        // zeros (layer-2 t=0)
__device__ unsigned g_ctr;                           // grid barrier counter

// ---------------- packed fp32x2 helpers ------------------------------------------
__device__ __forceinline__ u64 fma2(u64 a, u64 b, u64 c) {
    u64 d;
    asm("fma.rn.f32x2 %0, %1, %2, %3;" : "=l"(d) : "l"(a), "l"(b), "l"(c));
    return d;
}
__device__ __forceinline__ u64 mul2(u64 a, u64 b) {
    u64 d;
    asm("mul.rn.f32x2 %0, %1, %2;" : "=l"(d) : "l"(a), "l"(b));
    return d;
}
__device__ __forceinline__ float pairsum(u64 v) {
    float lo, hi;
    asm("mov.b64 {%0, %1}, %2;" : "=f"(lo), "=f"(hi) : "l"(v));
    return lo + hi;
}
__device__ __forceinline__ float sigm(float x) { return 1.0f / (1.0f + expf(-x)); }

// ---------------- warp GEMM segment with block pacing ----------------------------
// Warp tile (4j, 8b), k in lanes (4 f32/lane/iter), all LDG.128 coalesced.
// __syncthreads() every 512-k chunk keeps the block's 16 warps converged so L1
// serves the 4x intra-block weight/act line sharing.
template<bool RM>
__device__ __forceinline__ void segAcc(u64* acc,
    const float* __restrict__ wb, int ws,   // this warp's weight rows (4), stride
    const float* __restrict__ ab, int as,   // this warp's act rows (8), stride
    const float* __restrict__ rb,           // r rows (stride as) when RM
    int klen, int lane)
{
    for (int k0 = 0; k0 < klen; k0 += 512) {
        int kc = min(512, klen - k0);
        int off = k0 + (lane << 2);
        const int nIt = kc >> 7;
#pragma unroll 1
        for (int i = 0; i < nIt; i++, off += 128) {
            ulonglong2 w0 = *(const ulonglong2*)(wb + 0 * ws + off);
            ulonglong2 w1 = *(const ulonglong2*)(wb + 1 * ws + off);
            ulonglong2 w2 = *(const ulonglong2*)(wb + 2 * ws + off);
            ulonglong2 w3 = *(const ulonglong2*)(wb + 3 * ws + off);
#pragma unroll
            for (int bb = 0; bb < 8; bb++) {
                ulonglong2 a = *(const ulonglong2*)(ab + bb * as + off);
                if (RM) {
                    ulonglong2 rv = *(const ulonglong2*)(rb + bb * as + off);
                    a.x = mul2(rv.x, a.x);
                    a.y = mul2(rv.y, a.y);
                }
                acc[0 * 8 + bb] = fma2(w0.x, a.x, acc[0 * 8 + bb]);
                acc[0 * 8 + bb] = fma2(w0.y, a.y, acc[0 * 8 + bb]);
                acc[1 * 8 + bb] = fma2(w1.x, a.x, acc[1 * 8 + bb]);
                acc[1 * 8 + bb] = fma2(w1.y, a.y, acc[1 * 8 + bb]);
                acc[2 * 8 + bb] = fma2(w2.x, a.x, acc[2 * 8 + bb]);
                acc[2 * 8 + bb] = fma2(w2.y, a.y, acc[2 * 8 + bb]);
                acc[3 * 8 + bb] = fma2(w3.x, a.x, acc[3 * 8 + bb]);
                acc[3 * 8 + bb] = fma2(w3.y, a.y, acc[3 * 8 + bb]);
            }
        }
        __syncthreads();
    }
}

// ---------------- cross-lane reduce: lane L gets total of acc[L] ------------------
__device__ __forceinline__ float reduce32(u64* acc, int lane) {
    float v[32];
#pragma unroll
    for (int i = 0; i < 32; i++) v[i] = pairsum(acc[i]);
#pragma unroll
    for (int off = 16; off >= 1; off >>= 1) {
        bool hi = (lane & off) != 0;
#pragma unroll
        for (int i = 0; i < 16; i++) {
            if (i >= off) break;
            float send = hi ? v[i] : v[i + off];
            float recv = __shfl_xor_sync(0xffffffffu, send, off);
            v[i] = (hi ? v[i + off] : v[i]) + recv;
        }
    }
    return v[0];
}

// ---------------- software grid barrier -------------------------------------------
__device__ __forceinline__ void spinbar(unsigned target) {
    __syncthreads();
    if (threadIdx.x == 0) {
        __threadfence();
        atomicAdd(&g_ctr, 1u);
        while (*(volatile unsigned*)&g_ctr < target) { }
        __threadfence();
    }
    __syncthreads();
}

// ---------------- init --------------------------------------------------------------
__global__ void initZero() {
    int idx = blockIdx.x * blockDim.x + threadIdx.x;
    if (idx == 0) g_ctr = 0u;
    const int nh = 3 * 2 * B_ * H_;
    if (idx < nh) (&g_h[0][0][0])[idx] = 0.0f;
    else if (idx - nh < B_ * H_) g_hz[idx - nh] = 0.0f;
}

// ---------------- persistent GRU kernel ---------------------------------------------
// Block task = (combo, 16-j block, all 32 batches); 16 warps = 4 jsub x 4 bsub.
// Phase A: 576 tasks, cost-ordered. Phase B: 192 GRU tasks + 8 outHead tasks (s=tau-3).
__global__ void __launch_bounds__(TPB, 1) gruPersist(
    const float* __restrict__ x,
    const float* __restrict__ Wxz0, const float* __restrict__ Whz0, const float* __restrict__ bz0,
    const float* __restrict__ Wxr0, const float* __restrict__ Whr0, const float* __restrict__ br0,
    const float* __restrict__ Wxg0, const float* __restrict__ Whg0, const float* __restrict__ bg0,
    const float* __restrict__ Wxz,  const float* __restrict__ Whz,  const float* __restrict__ bz,
    const float* __restrict__ Wxr,  const float* __restrict__ Whr,  const float* __restrict__ br,
    const float* __restrict__ Wxg,  const float* __restrict__ Whg,  const float* __restrict__ bg,
    const float* __restrict__ Wout, const float* __restrict__ bout,
    float* __restrict__ out)
{
    const int w = threadIdx.x >> 5, lane = threadIdx.x & 31;
    const int jsub = w >> 2, bsub = w & 3;     // warp's 4-j / 8-b subtiles
    unsigned barn = 0;
    u64 acc[32];

    for (int tau = 0; tau < S_ + 3; tau++) {
        // ================= phase A: z, r, g-x =================
        for (int task = blockIdx.x; task < 576; task += GRID) {
            int l, gate, jblk;
            if (task < 256)      { int c = task >> 6; l = 1 + (c >> 1); gate = c & 1; jblk = task & 63; }
            else if (task < 384) { l = 0; gate = (task >> 6) & 1; jblk = task & 63; }
            else if (task < 512) { l = 1 + ((task - 384) >> 6); gate = 2; jblk = task & 63; }
            else                 { l = 0; gate = 2; jblk = task & 63; }
            int t = tau - l;
            if (t < 0 || t >= S_) continue;
            int J0 = jblk << 4;

            const float *Wx_p, *Wh_p, *bp;
            const float* inA; int Kin, inS;
            if (l == 0) {
                Wx_p = (gate == 0) ? Wxz0 : (gate == 1) ? Wxr0 : Wxg0;
                Wh_p = (gate == 0) ? Whz0 : Whr0;
                bp   = (gate == 0) ? bz0  : (gate == 1) ? br0  : bg0;
                Kin = I_; inA = x + t * I_; inS = S_ * I_;
            } else {
                int wo = (l - 1) * H_ * H_, bo = (l - 1) * H_;
                Wx_p = ((gate == 0) ? Wxz : (gate == 1) ? Wxr : Wxg) + wo;
                Wh_p = ((gate == 0) ? Whz : Whr) + wo;
                bp   = ((gate == 0) ? bz  : (gate == 1) ? br  : bg) + bo;
                Kin = H_; inA = g_h[l - 1][(tau + 1) & 1]; inS = H_;
            }

#pragma unroll
            for (int i = 0; i < 32; i++) acc[i] = 0ULL;
            segAcc<false>(acc, Wx_p + (J0 + jsub * 4) * Kin, Kin,
                          inA + bsub * 8 * inS, inS, 0, Kin, lane);
            if (gate < 2) {
                const float* hA = (l == 2) ? (t ? g_h2[t - 1] : g_hz)
                                           : g_h[l][(tau + 1) & 1];
                segAcc<false>(acc, Wh_p + (J0 + jsub * 4) * H_, H_,
                              hA + bsub * 8 * H_, H_, 0, H_, lane);
            }
            float s = reduce32(acc, lane);
            int j = J0 + jsub * 4 + (lane >> 3), b = bsub * 8 + (lane & 7);
            s += bp[j];
            if (gate == 0)      g_z[l][b * H_ + j] = sigm(s);
            else if (gate == 1) g_r[l][b * H_ + j] = sigm(s);
            else                g_gx[l][b * H_ + j] = s;
        }
        barn++; spinbar(barn * GRID);

        // ================= phase B: (r*h)@Whg^T + blend; outHead fill-in ==========
        for (int task = blockIdx.x; task < 200; task += GRID) {
            if (task < 192) {
                int l = task >> 6, jblk = task & 63;
                int t = tau - l;
                if (t < 0 || t >= S_) continue;
                int J0 = jblk << 4;
                const float* Wh_g = l ? (Whg + (l - 1) * H_ * H_) : Whg0;
                const float* hA = (l == 2) ? (t ? g_h2[t - 1] : g_hz)
                                           : g_h[l][(tau + 1) & 1];
#pragma unroll
                for (int i = 0; i < 32; i++) acc[i] = 0ULL;
                segAcc<true>(acc, Wh_g + (J0 + jsub * 4) * H_, H_,
                             hA + bsub * 8 * H_, H_,
                             &g_r[l][0] + bsub * 8 * H_, H_, lane);
                float s = reduce32(acc, lane);
                int j = J0 + jsub * 4 + (lane >> 3), b = bsub * 8 + (lane & 7);
                float gv = tanhf(g_gx[l][b * H_ + j] + s);
                float zv = g_z[l][b * H_ + j];
                float hold = hA[b * H_ + j];
                float hn = zv * hold + (1.0f - zv) * gv;
                float* hout = (l == 2) ? g_h2[t] : g_h[l][tau & 1];
                hout[b * H_ + j] = hn;
            } else {
                int s_t = tau - 3;
                if (s_t < 0 || s_t >= S_) continue;
                int J0 = (task - 192) << 4;   // 8 tasks x 16 o = 128
#pragma unroll
                for (int i = 0; i < 32; i++) acc[i] = 0ULL;
                segAcc<false>(acc, Wout + (J0 + jsub * 4) * H_, H_,
                              g_h2[s_t] + bsub * 8 * H_, H_, 0, H_, lane);
                float v = reduce32(acc, lane);
                int o = J0 + jsub * 4 + (lane >> 3), b = bsub * 8 + (lane & 7);
                out[b * (S_ * O_) + s_t * O_ + o] = v + bout[o];
            }
        }
        barn++; spinbar(barn * GRID);
    }
}

// ---------------- final hidden state: out2[b][l][j] ----------------------------------
__global__ void finalH(float* __restrict__ out) {
    int idx = blockIdx.x * blockDim.x + threadIdx.x;
    if (idx >= 3 * H_ * B_) return;
    int b = idx & 31;
    int j = (idx >> 5) & (H_ - 1);
    int l = idx >> 15;
    const float* src = (l == 2) ? g_h2[S_ - 1] : g_h[l][(S_ - 1 + l) & 1];
    out[B_ * S_ * O_ + b * (3 * H_) + l * H_ + j] = src[b * H_ + j];
}

// ---------------- host -----------------------------------------------------------------
extern "C" void kernel_launch(void* const* d_in, const int* in_sizes, int n_in,
                              void* d_out, int out_size) {
    const float* x    = (const float*)d_in[0];
    const float* Wxz0 = (const float*)d_in[1];
    const float* Whz0 = (const float*)d_in[2];
    const float* bz0  = (const float*)d_in[3];
    const float* Wxr0 = (const float*)d_in[4];
    const float* Whr0 = (const float*)d_in[5];
    const float* br0  = (const float*)d_in[6];
    const float* Wxg0 = (const float*)d_in[7];
    const float* Whg0 = (const float*)d_in[8];
    const float* bg0  = (const float*)d_in[9];
    const float* Wxz  = (const float*)d_in[10];
    const float* Whz  = (const float*)d_in[11];
    const float* bz   = (const float*)d_in[12];
    const float* Wxr  = (const float*)d_in[13];
    const float* Whr  = (const float*)d_in[14];
    const float* br   = (const float*)d_in[15];
    const float* Wxg  = (const float*)d_in[16];
    const float* Whg  = (const float*)d_in[17];
    const float* bg   = (const float*)d_in[18];
    const float* Wout = (const float*)d_in[19];
    const float* bout = (const float*)d_in[20];
    float* out = (float*)d_out;

    initZero<<<(3 * 2 * B_ * H_ + B_ * H_ + 255) / 256, 256>>>();

    gruPersist<<<GRID, TPB>>>(x,
        Wxz0, Whz0, bz0, Wxr0, Whr0, br0, Wxg0, Whg0, bg0,
        Wxz, Whz, bz, Wxr, Whr, br, Wxg, Whg, bg,
        Wout, bout, out);

    finalH<<<(3 * H_ * B_ + 255) / 256, 256>>>(out);
}